// round 5
// baseline (speedup 1.0000x reference)
#include <cuda_runtime.h>

#define BATCH    256
#define IN_CAPS  1152
#define NUM_CAPS 10
#define DIM_VEC  16
#define ITILE    8
#define NBLK_I   (IN_CAPS / ITILE)    // 144
#define B_TILE   32
#define NBLK_B   (BATCH / B_TILE)     // 8
#define NTH      640                  // (32 lanes) x (2 b-groups) x (10 c)
#define EPS 1e-7f

// Shared carve-up
#define WS_F   (ITILE * NUM_CAPS * 8 * DIM_VEC)  // 10240 floats (40 KB): [ii][c][e][d16]
#define XS_U   (ITILE * 8 * 33)                  // 2112 ull (16.9 KB): x dup-packed [j][bb]
#define VV_U   (NUM_CAPS * 8 * 33)               // 2640 ull (21.1 KB): [c][h*4+p][bb]
#define EX_F   (2 * B_TILE * 12)                 // 768 floats: exp exchange, stride 12
#define SMEM_BYTES (WS_F * 4 + (XS_U + VV_U) * 8 + EX_F * 4)   // ~81.9 KB

__device__ float g_sbuf[3][BATCH * NUM_CAPS * DIM_VEC];   // zero-init; final re-zeros
__device__ float g_blog[IN_CAPS * NUM_CAPS * BATCH];      // [i][c][b]

using ull = unsigned long long;
__device__ __forceinline__ ull pack2(float lo, float hi) {
    ull r; asm("mov.b64 %0,{%1,%2};" : "=l"(r) : "f"(lo), "f"(hi)); return r;
}
__device__ __forceinline__ void unpack2(ull v, float& lo, float& hi) {
    asm("mov.b64 {%0,%1},%2;" : "=f"(lo), "=f"(hi) : "l"(v));
}
__device__ __forceinline__ ull ffma2(ull a, ull b, ull c) {
    ull d; asm("fma.rn.f32x2 %0,%1,%2,%3;" : "=l"(d) : "l"(a), "l"(b), "l"(c)); return d;
}

// PASS 0: coef = softmax(bias); s0 += coef*u_hat
// PASS 1: v1=squash(s0); b1 = uh.v1 + 2*bias (store); s1 += softmax(b1)*u_hat
// PASS 2: v2=squash(s1); b2 = uh.v2 + b1 + bias;      s2 += softmax(b2)*u_hat
template <int PASS>
__global__ void __launch_bounds__(NTH, 2)
pass_kernel(const float* __restrict__ x,     // [256,1152,8]
            const float* __restrict__ W,     // [1152,10,16,8]
            const float* __restrict__ bias)  // [1152,10]
{
    extern __shared__ __align__(16) float sh[];
    float* ws  = sh;                       // W tile [ii][c][e][d16]
    ull*   xs  = (ull*)(sh + WS_F);        // x dup-packed [j][bb], stride 33
    ull*   vvs = xs + XS_U;                // v pairs [c*8 + h*4 + p][bb], stride 33
    float* exs = (float*)(vvs + VV_U);     // [2][32][12]

    const int xln = threadIdx.x;           // 0..31 (lane)
    const int h   = xln >> 4;              // d-half
    const int bl  = xln & 15;
    const int bg  = threadIdx.y;           // 0..1
    const int c   = threadIdx.z;           // 0..9
    const int bbl = bg * 16 + bl;          // 0..31 batch-in-tile
    const int tid = xln + 32 * bg + 64 * c;
    const int i0  = blockIdx.x * ITILE;
    const int b0  = blockIdx.y * B_TILE;
    const int b   = b0 + bbl;

    // ---- Stage W tile: global [i][c][d][e] (float4 = one d, e0..3) -> ws[ii][c][e][d]
    {
        const float4* Wg = (const float4*)(W + (size_t)i0 * NUM_CAPS * DIM_VEC * 8);
        #pragma unroll
        for (int k = tid; k < ITILE * NUM_CAPS * DIM_VEC * 2; k += NTH) {
            float4 w4 = Wg[k];                       // coalesced LDG.128
            int ii = k / (NUM_CAPS * DIM_VEC * 2);
            int r  = k - ii * (NUM_CAPS * DIM_VEC * 2);
            int cc = r >> 5;
            int d  = (r >> 1) & 15;
            int e0 = (r & 1) * 4;
            float* dst = ws + (((ii * NUM_CAPS + cc) * 8) + e0) * DIM_VEC + d;
            dst[0 * DIM_VEC] = w4.x;
            dst[1 * DIM_VEC] = w4.y;
            dst[2 * DIM_VEC] = w4.z;
            dst[3 * DIM_VEC] = w4.w;
        }
    }
    // ---- Stage x dup-packed: xs[j][bb] = (x,x)
    for (int t = tid; t < B_TILE * ITILE * 8; t += NTH) {
        int xlb = t >> 6;                            // b-in-tile
        int j   = t & 63;
        float v = x[(size_t)(b0 + xlb) * (IN_CAPS * 8) + i0 * 8 + j];
        xs[j * 33 + xlb] = pack2(v, v);
    }

    // ---- v = squash(s_prev): each thread owns its d-half; pairs go to shared
    ull* vr = vvs + (c * 8 + h * 4) * 33 + bbl;
    if (PASS > 0) {
        const float4* sp = (const float4*)(g_sbuf[PASS - 1] + (b * NUM_CAPS + c) * DIM_VEC + h * 8);
        float4 sa = sp[0], sb = sp[1];
        float sqh = sa.x * sa.x + sa.y * sa.y + sa.z * sa.z + sa.w * sa.w
                  + sb.x * sb.x + sb.y * sb.y + sb.z * sb.z + sb.w * sb.w;
        float sq = sqh + __shfl_xor_sync(0xffffffffu, sqh, 16);
        float scale = sq / (1.f + sq) * rsqrtf(sq + EPS);
        vr[0 * 33] = pack2(scale * sa.x, scale * sa.y);
        vr[1 * 33] = pack2(scale * sa.z, scale * sa.w);
        vr[2 * 33] = pack2(scale * sb.x, scale * sb.y);
        vr[3 * 33] = pack2(scale * sb.z, scale * sb.w);
    }
    __syncthreads();

    ull sacc[4] = {0ull, 0ull, 0ull, 0ull};
    const float* wcbase = ws + ((0 * NUM_CAPS + c) * 8) * DIM_VEC + h * 8;

    #pragma unroll 1
    for (int ii = 0; ii < ITILE; ii++) {
        const int i = i0 + ii;
        const float bs = __ldg(&bias[i * NUM_CAPS + c]);               // warp-uniform
        float bprev;
        if (PASS == 2) bprev = g_blog[(i * NUM_CAPS + c) * BATCH + b];

        // u_hat half (8 d's as 4 pairs): 16 LDS.128 + 8 LDS.64 + 32 FFMA2
        ull uh[4] = {0ull, 0ull, 0ull, 0ull};
        const float* wb = wcbase + ii * (NUM_CAPS * 8 * DIM_VEC);
        #pragma unroll
        for (int e = 0; e < 8; e++) {
            ull x2 = xs[(ii * 8 + e) * 33 + bbl];                      // dup-packed
            const ulonglong2* wp = (const ulonglong2*)(wb + e * DIM_VEC);
            ulonglong2 w0 = wp[0], w1 = wp[1];
            uh[0] = ffma2(w0.x, x2, uh[0]);
            uh[1] = ffma2(w0.y, x2, uh[1]);
            uh[2] = ffma2(w1.x, x2, uh[2]);
            uh[3] = ffma2(w1.y, x2, uh[3]);
        }

        float bnew;
        if (PASS == 0) {
            bnew = bs;
        } else {
            ull ag = 0ull;
            #pragma unroll
            for (int p = 0; p < 4; p++) ag = ffma2(uh[p], vr[p * 33], ag);
            float alo, ahi; unpack2(ag, alo, ahi);
            float agrh = alo + ahi;
            float agr = agrh + __shfl_xor_sync(0xffffffffu, agrh, 16); // partner half
            if (PASS == 1) {
                bnew = agr + 2.f * bs;
                if (h == 0) g_blog[(i * NUM_CAPS + c) * BATCH + b] = bnew;
            } else {
                bnew = agr + bprev + bs;
            }
        }

        // softmax over 10 c's, no max-subtract (bounded logits): 1 STS + 1 BAR
        float ex = __expf(bnew);
        const int pb = ii & 1;
        float* exr = exs + (pb * B_TILE + bbl) * 12;
        if (h == 0) exr[c] = ex;
        __syncthreads();
        float4 e0 = *(const float4*)(exr);
        float4 e1 = *(const float4*)(exr + 4);
        float2 e2 = *(const float2*)(exr + 8);
        float den = ((e0.x + e0.y) + (e0.z + e0.w))
                  + ((e1.x + e1.y) + (e1.z + e1.w)) + (e2.x + e2.y);
        float coef = __fdividef(ex, den);
        ull cf = pack2(coef, coef);
        #pragma unroll
        for (int p = 0; p < 4; p++) sacc[p] = ffma2(cf, uh[p], sacc[p]);
    }

    // partial s[b,c,h-half]: 2 vectored global reductions
    float* sp = g_sbuf[PASS] + (b * NUM_CAPS + c) * DIM_VEC + h * 8;
    float a0, a1, a2, a3;
    unpack2(sacc[0], a0, a1); unpack2(sacc[1], a2, a3);
    asm volatile("red.global.add.v4.f32 [%0], {%1,%2,%3,%4};"
                 :: "l"(sp), "f"(a0), "f"(a1), "f"(a2), "f"(a3) : "memory");
    unpack2(sacc[2], a0, a1); unpack2(sacc[3], a2, a3);
    asm volatile("red.global.add.v4.f32 [%0], {%1,%2,%3,%4};"
                 :: "l"(sp + 4), "f"(a0), "f"(a1), "f"(a2), "f"(a3) : "memory");
}

// out = squash(s2); re-zero all scratch for graph-replay determinism
__global__ void final_kernel(float* __restrict__ out)
{
    int t = blockIdx.x * blockDim.x + threadIdx.x;
    if (t < BATCH * NUM_CAPS) {
        float4* sp = (float4*)(g_sbuf[2] + t * DIM_VEC);
        float4 s4[4]; float sq = 0.f;
        #pragma unroll
        for (int q = 0; q < 4; q++) {
            s4[q] = sp[q];
            sq = fmaf(s4[q].x, s4[q].x, sq); sq = fmaf(s4[q].y, s4[q].y, sq);
            sq = fmaf(s4[q].z, s4[q].z, sq); sq = fmaf(s4[q].w, s4[q].w, sq);
        }
        float scale = sq / (1.f + sq) * rsqrtf(sq + EPS);
        float4* dst = (float4*)(out + t * DIM_VEC);
        float4 z = make_float4(0.f, 0.f, 0.f, 0.f);
        #pragma unroll
        for (int q = 0; q < 4; q++) {
            float4 o; o.x = scale * s4[q].x; o.y = scale * s4[q].y;
                      o.z = scale * s4[q].z; o.w = scale * s4[q].w;
            dst[q] = o;
            sp[q] = z;
        }
    }
    if (t < BATCH * NUM_CAPS * DIM_VEC) {
        g_sbuf[0][t] = 0.f;
        g_sbuf[1][t] = 0.f;
    }
}

extern "C" void kernel_launch(void* const* d_in, const int* in_sizes, int n_in,
                              void* d_out, int out_size)
{
    const float* x = nullptr; const float* W = nullptr; const float* bias = nullptr;
    for (int k = 0; k < n_in; k++) {
        if (in_sizes[k] == BATCH * IN_CAPS * 8)                    x    = (const float*)d_in[k];
        else if (in_sizes[k] == IN_CAPS * NUM_CAPS * DIM_VEC * 8)  W    = (const float*)d_in[k];
        else if (in_sizes[k] == IN_CAPS * NUM_CAPS)                bias = (const float*)d_in[k];
    }
    float* out = (float*)d_out;

    cudaFuncSetAttribute(pass_kernel<0>, cudaFuncAttributeMaxDynamicSharedMemorySize, SMEM_BYTES);
    cudaFuncSetAttribute(pass_kernel<1>, cudaFuncAttributeMaxDynamicSharedMemorySize, SMEM_BYTES);
    cudaFuncSetAttribute(pass_kernel<2>, cudaFuncAttributeMaxDynamicSharedMemorySize, SMEM_BYTES);

    dim3 blk(32, 2, NUM_CAPS);
    dim3 grd(NBLK_I, NBLK_B);
    pass_kernel<0><<<grd, blk, SMEM_BYTES>>>(x, W, bias);
    pass_kernel<1><<<grd, blk, SMEM_BYTES>>>(x, W, bias);
    pass_kernel<2><<<grd, blk, SMEM_BYTES>>>(x, W, bias);
    final_kernel<<<(BATCH * NUM_CAPS * DIM_VEC + 255) / 256, 256>>>(out);
}

// round 6
// speedup vs baseline: 1.1583x; 1.1583x over previous
#include <cuda_runtime.h>

#define BATCH    256
#define IN_CAPS  1152
#define NUM_CAPS 10
#define DIM_VEC  16
#define ITILE    12
#define NBLK_I   (IN_CAPS / ITILE)    // 96
#define B_TILE   32
#define NBLK_B   (BATCH / B_TILE)     // 8
#define NTH      (B_TILE * NUM_CAPS)  // 320
#define EPS 1e-7f

// Shared carve-up
#define WS_F   (ITILE * NUM_CAPS * 8 * DIM_VEC)  // 15360 floats: [ii][c][e][d16]
#define XS_F   (ITILE * 8 * 33)                  // 3168 floats : [j][bb] stride 33
#define VV_U   (NUM_CAPS * 8 * B_TILE)           // 2560 ull    : [c*8+p][bb]
#define EX_F   (4 * NUM_CAPS * B_TILE)           // 1280 floats : [slot][c][bb]
#define SMEM_BYTES ((WS_F + XS_F) * 4 + VV_U * 8 + EX_F * 4)   // 99712 B

__device__ float g_sbuf[3][BATCH * NUM_CAPS * DIM_VEC];   // zero-init; final re-zeros
__device__ float g_blog[IN_CAPS * NUM_CAPS * BATCH];      // [i][c][b]
__device__ float g_coef0[IN_CAPS * NUM_CAPS];             // softmax(bias) over c

using ull = unsigned long long;
__device__ __forceinline__ ull pack2(float lo, float hi) {
    ull r; asm("mov.b64 %0,{%1,%2};" : "=l"(r) : "f"(lo), "f"(hi)); return r;
}
__device__ __forceinline__ void unpack2(ull v, float& lo, float& hi) {
    asm("mov.b64 {%0,%1},%2;" : "=f"(lo), "=f"(hi) : "l"(v));
}
__device__ __forceinline__ ull ffma2(ull a, ull b, ull c) {
    ull d; asm("fma.rn.f32x2 %0,%1,%2,%3;" : "=l"(d) : "l"(a), "l"(b), "l"(c)); return d;
}

// coef0[i,c] = softmax_c(bias[i,c])  (b-independent -> pass0 needs no exchange)
__global__ void coef0_kernel(const float* __restrict__ bias)
{
    int i = blockIdx.x * blockDim.x + threadIdx.x;
    if (i >= IN_CAPS) return;
    float ex[NUM_CAPS]; float den = 0.f;
    #pragma unroll
    for (int k = 0; k < NUM_CAPS; k++) { ex[k] = __expf(bias[i * NUM_CAPS + k]); den += ex[k]; }
    float inv = __frcp_rn(den);
    #pragma unroll
    for (int k = 0; k < NUM_CAPS; k++) g_coef0[i * NUM_CAPS + k] = ex[k] * inv;
}

// PASS 0: s0 += coef0[i,c] * u_hat                      (no in-loop barriers)
// PASS 1: v1=squash(s0); b1 = uh.v1 + 2*bias (store); s1 += softmax(b1)*u_hat
// PASS 2: v2=squash(s1); b2 = uh.v2 + b1 + bias;      s2 += softmax(b2)*u_hat
template <int PASS>
__global__ void __launch_bounds__(NTH, 2)
pass_kernel(const float* __restrict__ x,     // [256,1152,8]
            const float* __restrict__ W,     // [1152,10,16,8]
            const float* __restrict__ bias)  // [1152,10]
{
    extern __shared__ __align__(16) float sh[];
    float* ws  = sh;                          // W tile
    float* xs  = sh + WS_F;                   // x tile
    ull*   vvs = (ull*)(sh + WS_F + XS_F);    // v pairs
    float* exs = (float*)(vvs + VV_U);        // exp exchange [4][10][32]

    const int tid = threadIdx.x;
    const int bb  = tid & 31;                 // lane = batch in tile
    const int c   = tid >> 5;                 // warp = capsule
    const int i0  = blockIdx.x * ITILE;
    const int b0  = blockIdx.y * B_TILE;
    const int b   = b0 + bb;

    // ---- Stage W tile: global [i][c][d][e] (float4 = d,e0..3) -> ws[ii][c][e][d]
    {
        const float4* Wg = (const float4*)(W + (size_t)i0 * NUM_CAPS * DIM_VEC * 8);
        #pragma unroll 2
        for (int k = tid; k < ITILE * NUM_CAPS * DIM_VEC * 2; k += NTH) {
            float4 w4 = Wg[k];                // coalesced LDG.128
            int ii = k / (NUM_CAPS * DIM_VEC * 2);
            int r  = k - ii * (NUM_CAPS * DIM_VEC * 2);
            int cc = r >> 5;
            int d  = (r >> 1) & 15;
            int e0 = (r & 1) * 4;
            float* dst = ws + (((ii * NUM_CAPS + cc) * 8) + e0) * DIM_VEC + d;
            dst[0 * DIM_VEC] = w4.x;
            dst[1 * DIM_VEC] = w4.y;
            dst[2 * DIM_VEC] = w4.z;
            dst[3 * DIM_VEC] = w4.w;
        }
    }
    // ---- Stage x tile transposed: xs[j][lb]
    for (int t = tid; t < B_TILE * ITILE * 8; t += NTH) {
        int lb = t / (ITILE * 8);
        int j  = t - lb * (ITILE * 8);
        xs[j * 33 + lb] = x[(size_t)(b0 + lb) * (IN_CAPS * 8) + i0 * 8 + j];
    }

    // ---- v = squash(s_prev) for (b,c) -> shared (conflict-free over bb)
    if (PASS > 0) {
        const float4* sp = (const float4*)(g_sbuf[PASS - 1] + (b * NUM_CAPS + c) * DIM_VEC);
        float4 s4[4]; float sq = 0.f;
        #pragma unroll
        for (int q = 0; q < 4; q++) {
            s4[q] = sp[q];
            sq = fmaf(s4[q].x, s4[q].x, sq); sq = fmaf(s4[q].y, s4[q].y, sq);
            sq = fmaf(s4[q].z, s4[q].z, sq); sq = fmaf(s4[q].w, s4[q].w, sq);
        }
        float scale = sq / (1.f + sq) * rsqrtf(sq + EPS);
        vvs[(c * 8 + 0) * B_TILE + bb] = pack2(scale * s4[0].x, scale * s4[0].y);
        vvs[(c * 8 + 1) * B_TILE + bb] = pack2(scale * s4[0].z, scale * s4[0].w);
        vvs[(c * 8 + 2) * B_TILE + bb] = pack2(scale * s4[1].x, scale * s4[1].y);
        vvs[(c * 8 + 3) * B_TILE + bb] = pack2(scale * s4[1].z, scale * s4[1].w);
        vvs[(c * 8 + 4) * B_TILE + bb] = pack2(scale * s4[2].x, scale * s4[2].y);
        vvs[(c * 8 + 5) * B_TILE + bb] = pack2(scale * s4[2].z, scale * s4[2].w);
        vvs[(c * 8 + 6) * B_TILE + bb] = pack2(scale * s4[3].x, scale * s4[3].y);
        vvs[(c * 8 + 7) * B_TILE + bb] = pack2(scale * s4[3].z, scale * s4[3].w);
    }
    __syncthreads();

    ull sacc[8];
    #pragma unroll
    for (int p = 0; p < 8; p++) sacc[p] = 0ull;

    if (PASS == 0) {
        // barrier-free streaming: s0 += coef0 * uh
        #pragma unroll 1
        for (int ii = 0; ii < ITILE; ii++) {
            const int i = i0 + ii;
            float coef = __ldg(&g_coef0[i * NUM_CAPS + c]);        // warp-uniform
            ull uh[8];
            #pragma unroll
            for (int p = 0; p < 8; p++) uh[p] = 0ull;
            const ulonglong2* wp = (const ulonglong2*)(ws + ((ii * NUM_CAPS + c) * 8) * DIM_VEC);
            #pragma unroll
            for (int e = 0; e < 8; e++) {
                float xv = xs[(ii * 8 + e) * 33 + bb];
                ull x2 = pack2(xv, xv);
                #pragma unroll
                for (int q = 0; q < 4; q++) {
                    ulonglong2 wv = wp[e * 4 + q];
                    uh[2 * q]     = ffma2(wv.x, x2, uh[2 * q]);
                    uh[2 * q + 1] = ffma2(wv.y, x2, uh[2 * q + 1]);
                }
            }
            ull cf = pack2(coef, coef);
            #pragma unroll
            for (int p = 0; p < 8; p++) sacc[p] = ffma2(cf, uh[p], sacc[p]);
        }
    } else {
        // 2-ii batching: one barrier per pair; 4-slot exchange (WAR-safe)
        #pragma unroll 1
        for (int iip = 0; iip < ITILE / 2; iip++) {
            const int slot0 = (iip & 1) * 2;
            ull uhA[8], uhB[8];
            float exA, exB;
            #pragma unroll
            for (int sub = 0; sub < 2; sub++) {
                const int ii = 2 * iip + sub;
                const int i  = i0 + ii;
                ull* uh = sub ? uhB : uhA;
                #pragma unroll
                for (int p = 0; p < 8; p++) uh[p] = 0ull;
                const ulonglong2* wp = (const ulonglong2*)(ws + ((ii * NUM_CAPS + c) * 8) * DIM_VEC);
                #pragma unroll
                for (int e = 0; e < 8; e++) {
                    float xv = xs[(ii * 8 + e) * 33 + bb];
                    ull x2 = pack2(xv, xv);
                    #pragma unroll
                    for (int q = 0; q < 4; q++) {
                        ulonglong2 wv = wp[e * 4 + q];
                        uh[2 * q]     = ffma2(wv.x, x2, uh[2 * q]);
                        uh[2 * q + 1] = ffma2(wv.y, x2, uh[2 * q + 1]);
                    }
                }
                // agreement: uh . v  (v from shared, conflict-free LDS.64)
                ull ag = 0ull;
                #pragma unroll
                for (int p = 0; p < 8; p++)
                    ag = ffma2(uh[p], vvs[(c * 8 + p) * B_TILE + bb], ag);
                float alo, ahi; unpack2(ag, alo, ahi);
                float agr = alo + ahi;
                const float bs = __ldg(&bias[i * NUM_CAPS + c]);   // warp-uniform
                float bnew;
                if (PASS == 1) {
                    bnew = agr + 2.f * bs;
                    g_blog[(i * NUM_CAPS + c) * BATCH + b] = bnew; // coalesced STG
                } else {
                    bnew = agr + g_blog[(i * NUM_CAPS + c) * BATCH + b] + bs;
                }
                float ex = __expf(bnew);                           // no max-subtract: bounded
                exs[(slot0 + sub) * (NUM_CAPS * B_TILE) + c * B_TILE + bb] = ex;
                if (sub == 0) exA = ex; else exB = ex;
            }
            __syncthreads();
            #pragma unroll
            for (int sub = 0; sub < 2; sub++) {
                const float* er = exs + (slot0 + sub) * (NUM_CAPS * B_TILE) + bb;
                float den = er[0];
                #pragma unroll
                for (int k = 1; k < NUM_CAPS; k++) den += er[k * B_TILE];  // conflict-free
                float coef = __fdividef(sub ? exB : exA, den);
                ull cf = pack2(coef, coef);
                const ull* uh = sub ? uhB : uhA;
                #pragma unroll
                for (int p = 0; p < 8; p++) sacc[p] = ffma2(cf, uh[p], sacc[p]);
            }
        }
    }

    // partial s[b,c,:] : 2 vectored global reductions (96 per address total)
    float* sp = g_sbuf[PASS] + (b * NUM_CAPS + c) * DIM_VEC;
    float a0, a1, a2, a3;
    unpack2(sacc[0], a0, a1); unpack2(sacc[1], a2, a3);
    asm volatile("red.global.add.v4.f32 [%0], {%1,%2,%3,%4};"
                 :: "l"(sp), "f"(a0), "f"(a1), "f"(a2), "f"(a3) : "memory");
    unpack2(sacc[2], a0, a1); unpack2(sacc[3], a2, a3);
    asm volatile("red.global.add.v4.f32 [%0], {%1,%2,%3,%4};"
                 :: "l"(sp + 4), "f"(a0), "f"(a1), "f"(a2), "f"(a3) : "memory");
    unpack2(sacc[4], a0, a1); unpack2(sacc[5], a2, a3);
    asm volatile("red.global.add.v4.f32 [%0], {%1,%2,%3,%4};"
                 :: "l"(sp + 8), "f"(a0), "f"(a1), "f"(a2), "f"(a3) : "memory");
    unpack2(sacc[6], a0, a1); unpack2(sacc[7], a2, a3);
    asm volatile("red.global.add.v4.f32 [%0], {%1,%2,%3,%4};"
                 :: "l"(sp + 12), "f"(a0), "f"(a1), "f"(a2), "f"(a3) : "memory");
}

// out = squash(s2); re-zero all scratch for graph-replay determinism
__global__ void final_kernel(float* __restrict__ out)
{
    int t = blockIdx.x * blockDim.x + threadIdx.x;
    if (t < BATCH * NUM_CAPS) {
        float4* sp = (float4*)(g_sbuf[2] + t * DIM_VEC);
        float4 s4[4]; float sq = 0.f;
        #pragma unroll
        for (int q = 0; q < 4; q++) {
            s4[q] = sp[q];
            sq = fmaf(s4[q].x, s4[q].x, sq); sq = fmaf(s4[q].y, s4[q].y, sq);
            sq = fmaf(s4[q].z, s4[q].z, sq); sq = fmaf(s4[q].w, s4[q].w, sq);
        }
        float scale = sq / (1.f + sq) * rsqrtf(sq + EPS);
        float4* dst = (float4*)(out + t * DIM_VEC);
        float4 z = make_float4(0.f, 0.f, 0.f, 0.f);
        #pragma unroll
        for (int q = 0; q < 4; q++) {
            float4 o; o.x = scale * s4[q].x; o.y = scale * s4[q].y;
                      o.z = scale * s4[q].z; o.w = scale * s4[q].w;
            dst[q] = o;
            sp[q] = z;
        }
    }
    if (t < BATCH * NUM_CAPS * DIM_VEC) {
        g_sbuf[0][t] = 0.f;
        g_sbuf[1][t] = 0.f;
    }
}

extern "C" void kernel_launch(void* const* d_in, const int* in_sizes, int n_in,
                              void* d_out, int out_size)
{
    const float* x = nullptr; const float* W = nullptr; const float* bias = nullptr;
    for (int k = 0; k < n_in; k++) {
        if (in_sizes[k] == BATCH * IN_CAPS * 8)                    x    = (const float*)d_in[k];
        else if (in_sizes[k] == IN_CAPS * NUM_CAPS * DIM_VEC * 8)  W    = (const float*)d_in[k];
        else if (in_sizes[k] == IN_CAPS * NUM_CAPS)                bias = (const float*)d_in[k];
    }
    float* out = (float*)d_out;

    cudaFuncSetAttribute(pass_kernel<0>, cudaFuncAttributeMaxDynamicSharedMemorySize, SMEM_BYTES);
    cudaFuncSetAttribute(pass_kernel<1>, cudaFuncAttributeMaxDynamicSharedMemorySize, SMEM_BYTES);
    cudaFuncSetAttribute(pass_kernel<2>, cudaFuncAttributeMaxDynamicSharedMemorySize, SMEM_BYTES);

    dim3 grd(NBLK_I, NBLK_B);
    coef0_kernel<<<(IN_CAPS + 127) / 128, 128>>>(bias);
    pass_kernel<0><<<grd, NTH, SMEM_BYTES>>>(x, W, bias);
    pass_kernel<1><<<grd, NTH, SMEM_BYTES>>>(x, W, bias);
    pass_kernel<2><<<grd, NTH, SMEM_BYTES>>>(x, W, bias);
    final_kernel<<<(BATCH * NUM_CAPS * DIM_VEC + 255) / 256, 256>>>(out);
}

// round 7
// speedup vs baseline: 1.1994x; 1.0355x over previous
#include <cuda_runtime.h>

#define BATCH    256
#define IN_CAPS  1152
#define NUM_CAPS 10
#define DIM_VEC  16
#define ITILE    12
#define NBLK_I   (IN_CAPS / ITILE)    // 96
#define B_TILE   64                   // 32 lanes x NB=2
#define NBLK_B   (BATCH / B_TILE)     // 4
#define NTH      320                  // 32 lanes x 10 c-warps
#define EPS 1e-7f

// Shared carve-up (floats)
#define WS_F   (ITILE * NUM_CAPS * 8 * DIM_VEC)  // 15360 : [ii][c][e][d16]
#define XS_F   (ITILE * 8 * 65)                  // 6240  : [j][bb64] stride 65
#define EX_F   (2 * NUM_CAPS * B_TILE)           // 1280  : [slot][c][bb64]
#define SMEM_BYTES ((WS_F + XS_F + EX_F) * 4)    // 91520 B

__device__ float g_sbuf[3][BATCH * NUM_CAPS * DIM_VEC];   // zero-init; final re-zeros
__device__ float g_blog[IN_CAPS * NUM_CAPS * BATCH];      // [i][c][b]
__device__ float g_coef0[IN_CAPS * NUM_CAPS];             // softmax(bias) over c

using ull = unsigned long long;
__device__ __forceinline__ ull pack2(float lo, float hi) {
    ull r; asm("mov.b64 %0,{%1,%2};" : "=l"(r) : "f"(lo), "f"(hi)); return r;
}
__device__ __forceinline__ void unpack2(ull v, float& lo, float& hi) {
    asm("mov.b64 {%0,%1},%2;" : "=f"(lo), "=f"(hi) : "l"(v));
}
__device__ __forceinline__ ull ffma2(ull a, ull b, ull c) {
    ull d; asm("fma.rn.f32x2 %0,%1,%2,%3;" : "=l"(d) : "l"(a), "l"(b), "l"(c)); return d;
}

// coef0[i,c] = softmax_c(bias[i,c])  (b-independent -> pass0 needs no exchange)
__global__ void coef0_kernel(const float* __restrict__ bias)
{
    int i = blockIdx.x * blockDim.x + threadIdx.x;
    if (i >= IN_CAPS) return;
    float ex[NUM_CAPS]; float den = 0.f;
    #pragma unroll
    for (int k = 0; k < NUM_CAPS; k++) { ex[k] = __expf(bias[i * NUM_CAPS + k]); den += ex[k]; }
    float inv = __frcp_rn(den);
    #pragma unroll
    for (int k = 0; k < NUM_CAPS; k++) g_coef0[i * NUM_CAPS + k] = ex[k] * inv;
}

__device__ __forceinline__ void load_v(const float* sprev, ull* vv)
{
    const float4* sp = (const float4*)sprev;
    float4 s4[4]; float sq = 0.f;
    #pragma unroll
    for (int q = 0; q < 4; q++) {
        s4[q] = sp[q];
        sq = fmaf(s4[q].x, s4[q].x, sq); sq = fmaf(s4[q].y, s4[q].y, sq);
        sq = fmaf(s4[q].z, s4[q].z, sq); sq = fmaf(s4[q].w, s4[q].w, sq);
    }
    float scale = sq / (1.f + sq) * rsqrtf(sq + EPS);
    #pragma unroll
    for (int q = 0; q < 4; q++) {
        vv[2 * q]     = pack2(scale * s4[q].x, scale * s4[q].y);
        vv[2 * q + 1] = pack2(scale * s4[q].z, scale * s4[q].w);
    }
}

// PASS 0: s0 += coef0[i,c] * u_hat                      (no in-loop barriers)
// PASS 1: v1=squash(s0); b1 = uh.v1 + 2*bias (store); s1 += softmax(b1)*u_hat
// PASS 2: v2=squash(s1); b2 = uh.v2 + b1 + bias;      s2 += softmax(b2)*u_hat
template <int PASS>
__global__ void __launch_bounds__(NTH)
pass_kernel(const float* __restrict__ x,     // [256,1152,8]
            const float* __restrict__ W,     // [1152,10,16,8]
            const float* __restrict__ bias)  // [1152,10]
{
    extern __shared__ __align__(16) float sh[];
    float* ws  = sh;                          // W tile [ii][c][e][d16]
    float* xs  = sh + WS_F;                   // x tile [j][bb64] stride 65
    float* exs = sh + WS_F + XS_F;            // exp exchange [2][c][bb64]

    const int tid = threadIdx.x;
    const int bb  = tid & 31;                 // lane
    const int c   = tid >> 5;                 // warp = capsule
    const int i0  = blockIdx.x * ITILE;
    const int b0  = blockIdx.y * B_TILE;
    const int bA  = b0 + bb;
    const int bB  = bA + 32;

    // ---- Stage W tile: global [i][c][d][e] (float4 = d,e0..3) -> ws[ii][c][e][d]
    {
        const float4* Wg = (const float4*)(W + (size_t)i0 * NUM_CAPS * DIM_VEC * 8);
        #pragma unroll 2
        for (int k = tid; k < ITILE * NUM_CAPS * DIM_VEC * 2; k += NTH) {
            float4 w4 = Wg[k];                // coalesced LDG.128
            int ii = k / (NUM_CAPS * DIM_VEC * 2);
            int r  = k - ii * (NUM_CAPS * DIM_VEC * 2);
            int cc = r >> 5;
            int d  = (r >> 1) & 15;
            int e0 = (r & 1) * 4;
            float* dst = ws + (((ii * NUM_CAPS + cc) * 8) + e0) * DIM_VEC + d;
            dst[0 * DIM_VEC] = w4.x;
            dst[1 * DIM_VEC] = w4.y;
            dst[2 * DIM_VEC] = w4.z;
            dst[3 * DIM_VEC] = w4.w;
        }
    }
    // ---- Stage x tile transposed: xs[j][lb], 64 batches
    for (int t = tid; t < B_TILE * ITILE * 8; t += NTH) {
        int lb = t / (ITILE * 8);
        int j  = t - lb * (ITILE * 8);
        xs[j * 65 + lb] = x[(size_t)(b0 + lb) * (IN_CAPS * 8) + i0 * 8 + j];
    }

    // ---- v = squash(s_prev) in REGISTERS for both batches
    ull vA[8], vB[8];
    if (PASS > 0) {
        load_v(g_sbuf[PASS - 1] + (bA * NUM_CAPS + c) * DIM_VEC, vA);
        load_v(g_sbuf[PASS - 1] + (bB * NUM_CAPS + c) * DIM_VEC, vB);
    }
    __syncthreads();

    ull saccA[8], saccB[8];
    #pragma unroll
    for (int p = 0; p < 8; p++) { saccA[p] = 0ull; saccB[p] = 0ull; }

    #pragma unroll 1
    for (int ii = 0; ii < ITILE; ii++) {
        const int i = i0 + ii;

        // u_hat for both batches: 32 uniform LDS.128 feed 128 FFMA2
        ull uhA[8], uhB[8];
        #pragma unroll
        for (int p = 0; p < 8; p++) { uhA[p] = 0ull; uhB[p] = 0ull; }
        const ulonglong2* wp = (const ulonglong2*)(ws + ((ii * NUM_CAPS + c) * 8) * DIM_VEC);
        #pragma unroll
        for (int e = 0; e < 8; e++) {
            float xvA = xs[(ii * 8 + e) * 65 + bb];
            float xvB = xs[(ii * 8 + e) * 65 + bb + 32];
            ull xa = pack2(xvA, xvA);
            ull xb = pack2(xvB, xvB);
            #pragma unroll
            for (int q = 0; q < 4; q++) {
                ulonglong2 wv = wp[e * 4 + q];
                uhA[2 * q]     = ffma2(wv.x, xa, uhA[2 * q]);
                uhA[2 * q + 1] = ffma2(wv.y, xa, uhA[2 * q + 1]);
                uhB[2 * q]     = ffma2(wv.x, xb, uhB[2 * q]);
                uhB[2 * q + 1] = ffma2(wv.y, xb, uhB[2 * q + 1]);
            }
        }

        if (PASS == 0) {
            float coef = __ldg(&g_coef0[i * NUM_CAPS + c]);       // warp-uniform
            ull cf = pack2(coef, coef);
            #pragma unroll
            for (int p = 0; p < 8; p++) {
                saccA[p] = ffma2(cf, uhA[p], saccA[p]);
                saccB[p] = ffma2(cf, uhB[p], saccB[p]);
            }
        } else {
            // agreement dots from register-resident v
            ull agA = 0ull, agB = 0ull;
            #pragma unroll
            for (int p = 0; p < 8; p++) {
                agA = ffma2(uhA[p], vA[p], agA);
                agB = ffma2(uhB[p], vB[p], agB);
            }
            float a0, a1; unpack2(agA, a0, a1); float agrA = a0 + a1;
            unpack2(agB, a0, a1);               float agrB = a0 + a1;

            const float bs = __ldg(&bias[i * NUM_CAPS + c]);      // warp-uniform
            float bnewA, bnewB;
            if (PASS == 1) {
                bnewA = agrA + 2.f * bs;
                bnewB = agrB + 2.f * bs;
                g_blog[(i * NUM_CAPS + c) * BATCH + bA] = bnewA;  // coalesced STG
                g_blog[(i * NUM_CAPS + c) * BATCH + bB] = bnewB;
            } else {
                bnewA = agrA + g_blog[(i * NUM_CAPS + c) * BATCH + bA] + bs;
                bnewB = agrB + g_blog[(i * NUM_CAPS + c) * BATCH + bB] + bs;
            }

            // softmax over 10 c's (no max-subtract: bounded logits)
            float exA = __expf(bnewA);
            float exB = __expf(bnewB);
            const int slot = ii & 1;
            float* er = exs + slot * (NUM_CAPS * B_TILE) + c * B_TILE;
            er[bb]      = exA;
            er[bb + 32] = exB;
            __syncthreads();
            const float* eb = exs + slot * (NUM_CAPS * B_TILE);
            float denA = eb[bb], denB = eb[bb + 32];
            #pragma unroll
            for (int k = 1; k < NUM_CAPS; k++) {                  // conflict-free LDS
                denA += eb[k * B_TILE + bb];
                denB += eb[k * B_TILE + bb + 32];
            }
            float cA = __fdividef(exA, denA);
            float cB = __fdividef(exB, denB);
            ull cfA = pack2(cA, cA);
            ull cfB = pack2(cB, cB);
            #pragma unroll
            for (int p = 0; p < 8; p++) {
                saccA[p] = ffma2(cfA, uhA[p], saccA[p]);
                saccB[p] = ffma2(cfB, uhB[p], saccB[p]);
            }
        }
    }

    // partials: 8 vectored global reductions (96 per address total)
    float a0, a1, a2, a3;
    float* spA = g_sbuf[PASS] + (bA * NUM_CAPS + c) * DIM_VEC;
    float* spB = g_sbuf[PASS] + (bB * NUM_CAPS + c) * DIM_VEC;
    #pragma unroll
    for (int q = 0; q < 4; q++) {
        unpack2(saccA[2 * q], a0, a1); unpack2(saccA[2 * q + 1], a2, a3);
        asm volatile("red.global.add.v4.f32 [%0], {%1,%2,%3,%4};"
                     :: "l"(spA + 4 * q), "f"(a0), "f"(a1), "f"(a2), "f"(a3) : "memory");
        unpack2(saccB[2 * q], a0, a1); unpack2(saccB[2 * q + 1], a2, a3);
        asm volatile("red.global.add.v4.f32 [%0], {%1,%2,%3,%4};"
                     :: "l"(spB + 4 * q), "f"(a0), "f"(a1), "f"(a2), "f"(a3) : "memory");
    }
}

// out = squash(s2); re-zero all scratch for graph-replay determinism
__global__ void final_kernel(float* __restrict__ out)
{
    int t = blockIdx.x * blockDim.x + threadIdx.x;
    if (t < BATCH * NUM_CAPS) {
        float4* sp = (float4*)(g_sbuf[2] + t * DIM_VEC);
        float4 s4[4]; float sq = 0.f;
        #pragma unroll
        for (int q = 0; q < 4; q++) {
            s4[q] = sp[q];
            sq = fmaf(s4[q].x, s4[q].x, sq); sq = fmaf(s4[q].y, s4[q].y, sq);
            sq = fmaf(s4[q].z, s4[q].z, sq); sq = fmaf(s4[q].w, s4[q].w, sq);
        }
        float scale = sq / (1.f + sq) * rsqrtf(sq + EPS);
        float4* dst = (float4*)(out + t * DIM_VEC);
        float4 z = make_float4(0.f, 0.f, 0.f, 0.f);
        #pragma unroll
        for (int q = 0; q < 4; q++) {
            float4 o; o.x = scale * s4[q].x; o.y = scale * s4[q].y;
                      o.z = scale * s4[q].z; o.w = scale * s4[q].w;
            dst[q] = o;
            sp[q] = z;
        }
    }
    if (t < BATCH * NUM_CAPS * DIM_VEC) {
        g_sbuf[0][t] = 0.f;
        g_sbuf[1][t] = 0.f;
    }
}

extern "C" void kernel_launch(void* const* d_in, const int* in_sizes, int n_in,
                              void* d_out, int out_size)
{
    const float* x = nullptr; const float* W = nullptr; const float* bias = nullptr;
    for (int k = 0; k < n_in; k++) {
        if (in_sizes[k] == BATCH * IN_CAPS * 8)                    x    = (const float*)d_in[k];
        else if (in_sizes[k] == IN_CAPS * NUM_CAPS * DIM_VEC * 8)  W    = (const float*)d_in[k];
        else if (in_sizes[k] == IN_CAPS * NUM_CAPS)                bias = (const float*)d_in[k];
    }
    float* out = (float*)d_out;

    cudaFuncSetAttribute(pass_kernel<0>, cudaFuncAttributeMaxDynamicSharedMemorySize, SMEM_BYTES);
    cudaFuncSetAttribute(pass_kernel<1>, cudaFuncAttributeMaxDynamicSharedMemorySize, SMEM_BYTES);
    cudaFuncSetAttribute(pass_kernel<2>, cudaFuncAttributeMaxDynamicSharedMemorySize, SMEM_BYTES);

    dim3 grd(NBLK_I, NBLK_B);
    coef0_kernel<<<(IN_CAPS + 127) / 128, 128>>>(bias);
    pass_kernel<0><<<grd, NTH, SMEM_BYTES>>>(x, W, bias);
    pass_kernel<1><<<grd, NTH, SMEM_BYTES>>>(x, W, bias);
    pass_kernel<2><<<grd, NTH, SMEM_BYTES>>>(x, W, bias);
    final_kernel<<<(BATCH * NUM_CAPS * DIM_VEC + 255) / 256, 256>>>(out);
}

// round 8
// speedup vs baseline: 1.3729x; 1.1447x over previous
#include <cuda_runtime.h>

#define BATCH    256
#define IN_CAPS  1152
#define NUM_CAPS 10
#define DIM_VEC  16
#define ITILE    16
#define NBLK_I   (IN_CAPS / ITILE)    // 72
#define B_TILE   32
#define NBLK_B   (BATCH / B_TILE)     // 8
#define NTH      (B_TILE * NUM_CAPS)  // 320
#define EPS 1e-7f

// Shared carve-up (floats)
#define WS_F   (ITILE * NUM_CAPS * 8 * DIM_VEC)  // 20480 : [ii][c][e][d16]
#define XS_F   (ITILE * 8 * 33)                  // 4224  : [j][bb] stride 33
#define EX_F   (2 * B_TILE * 11)                 // 704   : [slot][bb][c] stride 11
#define CF_F   (ITILE * NUM_CAPS)                // 160   : coef0 tile (pass0)
#define SMEM_BYTES ((WS_F + XS_F + EX_F + CF_F) * 4)   // 102272 B

__device__ float g_sbuf[3][BATCH * NUM_CAPS * DIM_VEC];   // zero-init; final re-zeros
__device__ float g_blog[IN_CAPS * NUM_CAPS * BATCH];      // [i][c][b]

using ull = unsigned long long;
__device__ __forceinline__ ull pack2(float lo, float hi) {
    ull r; asm("mov.b64 %0,{%1,%2};" : "=l"(r) : "f"(lo), "f"(hi)); return r;
}
__device__ __forceinline__ void unpack2(ull v, float& lo, float& hi) {
    asm("mov.b64 {%0,%1},%2;" : "=f"(lo), "=f"(hi) : "l"(v));
}
__device__ __forceinline__ ull ffma2(ull a, ull b, ull c) {
    ull d; asm("fma.rn.f32x2 %0,%1,%2,%3;" : "=l"(d) : "l"(a), "l"(b), "l"(c)); return d;
}

// PASS 0: s0 += softmax_c(bias) * u_hat            (no in-loop barriers/exchange)
// PASS 1: v1=squash(s0); b1 = uh.v1 + 2*bias (store); s1 += softmax(b1)*u_hat
// PASS 2: v2=squash(s1); b2 = uh.v2 + b1 + bias;      s2 += softmax(b2)*u_hat
template <int PASS>
__global__ void __launch_bounds__(NTH, 2)
pass_kernel(const float* __restrict__ x,     // [256,1152,8]
            const float* __restrict__ W,     // [1152,10,16,8]
            const float* __restrict__ bias)  // [1152,10]
{
    extern __shared__ __align__(16) float sh[];
    float* ws  = sh;                          // W tile [ii][c][e][d16]
    float* xs  = sh + WS_F;                   // x tile [j][bb] stride 33
    float* exs = sh + WS_F + XS_F;            // exchange [2][bb][c] stride 11
    float* cfs = exs + EX_F;                  // coef0 tile [ii][c] (pass0 only)

    const int tid = threadIdx.x;
    const int bb  = tid & 31;                 // lane = batch in tile
    const int c   = tid >> 5;                 // warp = capsule
    const int i0  = blockIdx.x * ITILE;
    const int b0  = blockIdx.y * B_TILE;
    const int b   = b0 + bb;

    // ---- Stage W tile: global [i][c][d][e] (float4 = d,e0..3) -> ws[ii][c][e][d]
    {
        const float4* Wg = (const float4*)(W + (size_t)i0 * NUM_CAPS * DIM_VEC * 8);
        #pragma unroll 2
        for (int k = tid; k < ITILE * NUM_CAPS * DIM_VEC * 2; k += NTH) {
            float4 w4 = Wg[k];                // coalesced LDG.128
            int ii = k / (NUM_CAPS * DIM_VEC * 2);
            int r  = k - ii * (NUM_CAPS * DIM_VEC * 2);
            int cc = r >> 5;
            int d  = (r >> 1) & 15;
            int e0 = (r & 1) * 4;
            float* dst = ws + (((ii * NUM_CAPS + cc) * 8) + e0) * DIM_VEC + d;
            dst[0 * DIM_VEC] = w4.x;
            dst[1 * DIM_VEC] = w4.y;
            dst[2 * DIM_VEC] = w4.z;
            dst[3 * DIM_VEC] = w4.w;
        }
    }
    // ---- Stage x tile transposed: xs[j][lb]
    for (int t = tid; t < B_TILE * ITILE * 8; t += NTH) {
        int lb = t >> 7;
        int j  = t & 127;
        xs[j * 33 + lb] = x[(size_t)(b0 + lb) * (IN_CAPS * 8) + i0 * 8 + j];
    }
    // ---- Pass0: coef0[ii][c] = softmax_c(bias[i0+ii, :]) computed by ITILE threads
    if (PASS == 0 && tid < ITILE) {
        const float* bp = bias + (i0 + tid) * NUM_CAPS;
        float ex[NUM_CAPS]; float den = 0.f;
        #pragma unroll
        for (int k = 0; k < NUM_CAPS; k++) { ex[k] = __expf(bp[k]); den += ex[k]; }
        float inv = __frcp_rn(den);
        #pragma unroll
        for (int k = 0; k < NUM_CAPS; k++) cfs[tid * NUM_CAPS + k] = ex[k] * inv;
    }

    // ---- v = squash(s_prev) for this (b,c): REGISTER-resident (key to R4 speed)
    ull vv[8];
    if (PASS > 0) {
        const float4* sp = (const float4*)(g_sbuf[PASS - 1] + (b * NUM_CAPS + c) * DIM_VEC);
        float4 s4[4]; float sq = 0.f;
        #pragma unroll
        for (int q = 0; q < 4; q++) {
            s4[q] = sp[q];
            sq = fmaf(s4[q].x, s4[q].x, sq); sq = fmaf(s4[q].y, s4[q].y, sq);
            sq = fmaf(s4[q].z, s4[q].z, sq); sq = fmaf(s4[q].w, s4[q].w, sq);
        }
        float scale = sq / (1.f + sq) * rsqrtf(sq + EPS);
        #pragma unroll
        for (int q = 0; q < 4; q++) {
            vv[2 * q]     = pack2(scale * s4[q].x, scale * s4[q].y);
            vv[2 * q + 1] = pack2(scale * s4[q].z, scale * s4[q].w);
        }
    }
    __syncthreads();

    ull sacc[8];
    #pragma unroll
    for (int p = 0; p < 8; p++) sacc[p] = 0ull;

    #pragma unroll 1
    for (int ii = 0; ii < ITILE; ii++) {
        const int i = i0 + ii;

        // u_hat[c,0..15] as 8 pairs: 32 warp-uniform LDS.128 + 64 FFMA2
        ull uh[8];
        #pragma unroll
        for (int p = 0; p < 8; p++) uh[p] = 0ull;
        const ulonglong2* wp = (const ulonglong2*)(ws + ((ii * NUM_CAPS + c) * 8) * DIM_VEC);
        #pragma unroll
        for (int e = 0; e < 8; e++) {
            float xv = xs[(ii * 8 + e) * 33 + bb];            // conflict-free
            ull x2 = pack2(xv, xv);
            #pragma unroll
            for (int q = 0; q < 4; q++) {
                ulonglong2 wv = wp[e * 4 + q];
                uh[2 * q]     = ffma2(wv.x, x2, uh[2 * q]);
                uh[2 * q + 1] = ffma2(wv.y, x2, uh[2 * q + 1]);
            }
        }

        float coef;
        if (PASS == 0) {
            coef = cfs[ii * NUM_CAPS + c];                    // warp-uniform LDS
        } else {
            // agreement from register-resident v
            ull ag = 0ull;
            #pragma unroll
            for (int p = 0; p < 8; p++) ag = ffma2(uh[p], vv[p], ag);
            float alo, ahi; unpack2(ag, alo, ahi);
            float agr = alo + ahi;

            const float bs = __ldg(&bias[i * NUM_CAPS + c]);  // warp-uniform
            float bnew;
            if (PASS == 1) {
                bnew = agr + 2.f * bs;
                g_blog[(i * NUM_CAPS + c) * BATCH + b] = bnew;   // coalesced STG
            } else {
                bnew = agr + g_blog[(i * NUM_CAPS + c) * BATCH + b] + bs;
            }

            // softmax over 10 c's, no max-subtract (bounded logits)
            float ex = __expf(bnew);
            const int pb = ii & 1;
            float* exr = exs + (pb * B_TILE + bb) * 11;       // stride 11: conflict-free
            exr[c] = ex;
            __syncthreads();
            // 10 independent loads + tree add (short post-barrier critical path)
            float t0 = exr[0], t1 = exr[1], t2 = exr[2], t3 = exr[3], t4 = exr[4];
            float t5 = exr[5], t6 = exr[6], t7 = exr[7], t8 = exr[8], t9 = exr[9];
            float den = ((t0 + t1) + (t2 + t3)) + ((t4 + t5) + (t6 + t7)) + (t8 + t9);
            coef = __fdividef(ex, den);
        }

        ull cf = pack2(coef, coef);
        #pragma unroll
        for (int p = 0; p < 8; p++) sacc[p] = ffma2(cf, uh[p], sacc[p]);
    }

    // partial s[b,c,:] : 4 vectored global reductions (72 per address total)
    float* sp = g_sbuf[PASS] + (b * NUM_CAPS + c) * DIM_VEC;
    float a0, a1, a2, a3;
    #pragma unroll
    for (int q = 0; q < 4; q++) {
        unpack2(sacc[2 * q], a0, a1); unpack2(sacc[2 * q + 1], a2, a3);
        asm volatile("red.global.add.v4.f32 [%0], {%1,%2,%3,%4};"
                     :: "l"(sp + 4 * q), "f"(a0), "f"(a1), "f"(a2), "f"(a3) : "memory");
    }
}

// out = squash(s2); re-zero all scratch for graph-replay determinism
__global__ void final_kernel(float* __restrict__ out)
{
    int t = blockIdx.x * blockDim.x + threadIdx.x;
    if (t < BATCH * NUM_CAPS) {
        float4* sp = (float4*)(g_sbuf[2] + t * DIM_VEC);
        float4 s4[4]; float sq = 0.f;
        #pragma unroll
        for (int q = 0; q < 4; q++) {
            s4[q] = sp[q];
            sq = fmaf(s4[q].x, s4[q].x, sq); sq = fmaf(s4[q].y, s4[q].y, sq);
            sq = fmaf(s4[q].z, s4[q].z, sq); sq = fmaf(s4[q].w, s4[q].w, sq);
        }
        float scale = sq / (1.f + sq) * rsqrtf(sq + EPS);
        float4* dst = (float4*)(out + t * DIM_VEC);
        float4 z = make_float4(0.f, 0.f, 0.f, 0.f);
        #pragma unroll
        for (int q = 0; q < 4; q++) {
            float4 o; o.x = scale * s4[q].x; o.y = scale * s4[q].y;
                      o.z = scale * s4[q].z; o.w = scale * s4[q].w;
            dst[q] = o;
            sp[q] = z;
        }
    }
    if (t < BATCH * NUM_CAPS * DIM_VEC) {
        g_sbuf[0][t] = 0.f;
        g_sbuf[1][t] = 0.f;
    }
}

extern "C" void kernel_launch(void* const* d_in, const int* in_sizes, int n_in,
                              void* d_out, int out_size)
{
    const float* x = nullptr; const float* W = nullptr; const float* bias = nullptr;
    for (int k = 0; k < n_in; k++) {
        if (in_sizes[k] == BATCH * IN_CAPS * 8)                    x    = (const float*)d_in[k];
        else if (in_sizes[k] == IN_CAPS * NUM_CAPS * DIM_VEC * 8)  W    = (const float*)d_in[k];
        else if (in_sizes[k] == IN_CAPS * NUM_CAPS)                bias = (const float*)d_in[k];
    }
    float* out = (float*)d_out;

    cudaFuncSetAttribute(pass_kernel<0>, cudaFuncAttributeMaxDynamicSharedMemorySize, SMEM_BYTES);
    cudaFuncSetAttribute(pass_kernel<1>, cudaFuncAttributeMaxDynamicSharedMemorySize, SMEM_BYTES);
    cudaFuncSetAttribute(pass_kernel<2>, cudaFuncAttributeMaxDynamicSharedMemorySize, SMEM_BYTES);

    dim3 grd(NBLK_I, NBLK_B);
    pass_kernel<0><<<grd, NTH, SMEM_BYTES>>>(x, W, bias);
    pass_kernel<1><<<grd, NTH, SMEM_BYTES>>>(x, W, bias);
    pass_kernel<2><<<grd, NTH, SMEM_BYTES>>>(x, W, bias);
    final_kernel<<<(BATCH * NUM_CAPS * DIM_VEC + 255) / 256, 256>>>(out);
}

// round 9
// speedup vs baseline: 1.4131x; 1.0293x over previous
#include <cuda_runtime.h>

#define BATCH    256
#define IN_CAPS  1152
#define NUM_CAPS 10
#define DIM_VEC  16
#define ITILE    16
#define NBLK_I   (IN_CAPS / ITILE)    // 72
#define B_TILE   32
#define NBLK_B   (BATCH / B_TILE)     // 8
#define NTH      (B_TILE * NUM_CAPS)  // 320
#define EPS 1e-7f

// Shared carve-up (floats)
#define WS_F   (ITILE * NUM_CAPS * 8 * DIM_VEC)  // 20480 : [ii][c][e][d16]
#define XS_F   (ITILE * 8 * 33)                  // 4224  : [j][bb] stride 33
#define EX_F   (4 * B_TILE * 11)                 // 1408  : [slot][bb][c] stride 11
#define CF_F   (ITILE * NUM_CAPS)                // 160   : coef0 tile (pass0)
#define SMEM_BYTES ((WS_F + XS_F + EX_F + CF_F) * 4)   // 105088 B

__device__ float g_sbuf[3][BATCH * NUM_CAPS * DIM_VEC];   // zero-init; final re-zeros
__device__ float g_blog[IN_CAPS * NUM_CAPS * BATCH];      // [i][c][b]

using ull = unsigned long long;
__device__ __forceinline__ ull pack2(float lo, float hi) {
    ull r; asm("mov.b64 %0,{%1,%2};" : "=l"(r) : "f"(lo), "f"(hi)); return r;
}
__device__ __forceinline__ void unpack2(ull v, float& lo, float& hi) {
    asm("mov.b64 {%0,%1},%2;" : "=f"(lo), "=f"(hi) : "l"(v));
}
__device__ __forceinline__ ull ffma2(ull a, ull b, ull c) {
    ull d; asm("fma.rn.f32x2 %0,%1,%2,%3;" : "=l"(d) : "l"(a), "l"(b), "l"(c)); return d;
}

// PASS 0: s0 += softmax_c(bias) * u_hat            (no in-loop barriers/exchange)
// PASS 1: v1=squash(s0); b1 = uh.v1 + 2*bias (store); s1 += softmax(b1)*u_hat
// PASS 2: v2=squash(s1); b2 = uh.v2 + b1 + bias;      s2 += softmax(b2)*u_hat
template <int PASS>
__global__ void __launch_bounds__(NTH, 2)
pass_kernel(const float* __restrict__ x,     // [256,1152,8]
            const float* __restrict__ W,     // [1152,10,16,8]
            const float* __restrict__ bias)  // [1152,10]
{
    extern __shared__ __align__(16) float sh[];
    float* ws  = sh;                          // W tile [ii][c][e][d16]
    float* xs  = sh + WS_F;                   // x tile [j][bb] stride 33
    float* exs = sh + WS_F + XS_F;            // exchange [4][bb][c] stride 11
    float* cfs = exs + EX_F;                  // coef0 tile [ii][c] (pass0 only)

    const int tid = threadIdx.x;
    const int bb  = tid & 31;                 // lane = batch in tile
    const int c   = tid >> 5;                 // warp = capsule
    const int i0  = blockIdx.x * ITILE;
    const int b0  = blockIdx.y * B_TILE;
    const int b   = b0 + bb;

    // ---- Stage W tile: global [i][c][d][e] (float4 = d,e0..3) -> ws[ii][c][e][d]
    {
        const float4* Wg = (const float4*)(W + (size_t)i0 * NUM_CAPS * DIM_VEC * 8);
        #pragma unroll 2
        for (int k = tid; k < ITILE * NUM_CAPS * DIM_VEC * 2; k += NTH) {
            float4 w4 = Wg[k];                // coalesced LDG.128
            int ii = k / (NUM_CAPS * DIM_VEC * 2);
            int r  = k - ii * (NUM_CAPS * DIM_VEC * 2);
            int cc = r >> 5;
            int d  = (r >> 1) & 15;
            int e0 = (r & 1) * 4;
            float* dst = ws + (((ii * NUM_CAPS + cc) * 8) + e0) * DIM_VEC + d;
            dst[0 * DIM_VEC] = w4.x;
            dst[1 * DIM_VEC] = w4.y;
            dst[2 * DIM_VEC] = w4.z;
            dst[3 * DIM_VEC] = w4.w;
        }
    }
    // ---- Stage x tile transposed: xs[j][lb]
    for (int t = tid; t < B_TILE * ITILE * 8; t += NTH) {
        int lb = t >> 7;
        int j  = t & 127;
        xs[j * 33 + lb] = x[(size_t)(b0 + lb) * (IN_CAPS * 8) + i0 * 8 + j];
    }
    // ---- Pass0: coef0[ii][c] = softmax_c(bias[i0+ii, :]) computed by ITILE threads
    if (PASS == 0 && tid < ITILE) {
        const float* bp = bias + (i0 + tid) * NUM_CAPS;
        float ex[NUM_CAPS]; float den = 0.f;
        #pragma unroll
        for (int k = 0; k < NUM_CAPS; k++) { ex[k] = __expf(bp[k]); den += ex[k]; }
        float inv = __frcp_rn(den);
        #pragma unroll
        for (int k = 0; k < NUM_CAPS; k++) cfs[tid * NUM_CAPS + k] = ex[k] * inv;
    }

    // ---- v = squash(s_prev) for this (b,c): REGISTER-resident
    ull vv[8];
    if (PASS > 0) {
        const float4* sp = (const float4*)(g_sbuf[PASS - 1] + (b * NUM_CAPS + c) * DIM_VEC);
        float4 s4[4]; float sq = 0.f;
        #pragma unroll
        for (int q = 0; q < 4; q++) {
            s4[q] = sp[q];
            sq = fmaf(s4[q].x, s4[q].x, sq); sq = fmaf(s4[q].y, s4[q].y, sq);
            sq = fmaf(s4[q].z, s4[q].z, sq); sq = fmaf(s4[q].w, s4[q].w, sq);
        }
        float scale = sq / (1.f + sq) * rsqrtf(sq + EPS);
        #pragma unroll
        for (int q = 0; q < 4; q++) {
            vv[2 * q]     = pack2(scale * s4[q].x, scale * s4[q].y);
            vv[2 * q + 1] = pack2(scale * s4[q].z, scale * s4[q].w);
        }
    }
    __syncthreads();

    ull sacc[8];
    #pragma unroll
    for (int p = 0; p < 8; p++) sacc[p] = 0ull;

    if (PASS == 0) {
        // barrier-free streaming
        #pragma unroll 1
        for (int ii = 0; ii < ITILE; ii++) {
            ull uh[8];
            #pragma unroll
            for (int p = 0; p < 8; p++) uh[p] = 0ull;
            const ulonglong2* wp = (const ulonglong2*)(ws + ((ii * NUM_CAPS + c) * 8) * DIM_VEC);
            #pragma unroll
            for (int e = 0; e < 8; e++) {
                float xv = xs[(ii * 8 + e) * 33 + bb];
                ull x2 = pack2(xv, xv);
                #pragma unroll
                for (int q = 0; q < 4; q++) {
                    ulonglong2 wv = wp[e * 4 + q];
                    uh[2 * q]     = ffma2(wv.x, x2, uh[2 * q]);
                    uh[2 * q + 1] = ffma2(wv.y, x2, uh[2 * q + 1]);
                }
            }
            float coef = cfs[ii * NUM_CAPS + c];              // warp-uniform LDS
            ull cf = pack2(coef, coef);
            #pragma unroll
            for (int p = 0; p < 8; p++) sacc[p] = ffma2(cf, uh[p], sacc[p]);
        }
    } else {
        // 2-ii software pipeline: one barrier per pair, 4-slot WAR-safe exchange
        #pragma unroll 1
        for (int iip = 0; iip < ITILE / 2; iip++) {
            const int slot0 = (iip & 1) * 2;
            ull uhA[8], uhB[8];
            float exA, exB;
            #pragma unroll
            for (int sub = 0; sub < 2; sub++) {
                const int ii = 2 * iip + sub;
                const int i  = i0 + ii;
                ull* uh = sub ? uhB : uhA;
                #pragma unroll
                for (int p = 0; p < 8; p++) uh[p] = 0ull;
                const ulonglong2* wp = (const ulonglong2*)(ws + ((ii * NUM_CAPS + c) * 8) * DIM_VEC);
                #pragma unroll
                for (int e = 0; e < 8; e++) {
                    float xv = xs[(ii * 8 + e) * 33 + bb];    // conflict-free
                    ull x2 = pack2(xv, xv);
                    #pragma unroll
                    for (int q = 0; q < 4; q++) {
                        ulonglong2 wv = wp[e * 4 + q];
                        uh[2 * q]     = ffma2(wv.x, x2, uh[2 * q]);
                        uh[2 * q + 1] = ffma2(wv.y, x2, uh[2 * q + 1]);
                    }
                }
                // agreement from register-resident v
                ull ag = 0ull;
                #pragma unroll
                for (int p = 0; p < 8; p++) ag = ffma2(uh[p], vv[p], ag);
                float alo, ahi; unpack2(ag, alo, ahi);
                float agr = alo + ahi;

                const float bs = __ldg(&bias[i * NUM_CAPS + c]);   // warp-uniform
                float bnew;
                if (PASS == 1) {
                    bnew = agr + 2.f * bs;
                    g_blog[(i * NUM_CAPS + c) * BATCH + b] = bnew; // coalesced STG
                } else {
                    bnew = agr + g_blog[(i * NUM_CAPS + c) * BATCH + b] + bs;
                }
                float ex = __expf(bnew);                      // no max-subtract: bounded
                exs[((slot0 + sub) * B_TILE + bb) * 11 + c] = ex;
                if (sub == 0) exA = ex; else exB = ex;
            }
            __syncthreads();                                  // ONE barrier per 2 ii
            #pragma unroll
            for (int sub = 0; sub < 2; sub++) {
                const float* exr = exs + ((slot0 + sub) * B_TILE + bb) * 11;
                float t0 = exr[0], t1 = exr[1], t2 = exr[2], t3 = exr[3], t4 = exr[4];
                float t5 = exr[5], t6 = exr[6], t7 = exr[7], t8 = exr[8], t9 = exr[9];
                float den = ((t0 + t1) + (t2 + t3)) + ((t4 + t5) + (t6 + t7)) + (t8 + t9);
                float coef = __fdividef(sub ? exB : exA, den);
                ull cf = pack2(coef, coef);
                const ull* uh = sub ? uhB : uhA;
                #pragma unroll
                for (int p = 0; p < 8; p++) sacc[p] = ffma2(cf, uh[p], sacc[p]);
            }
        }
    }

    // partial s[b,c,:] : 4 vectored global reductions (72 per address total)
    float* sp = g_sbuf[PASS] + (b * NUM_CAPS + c) * DIM_VEC;
    float a0, a1, a2, a3;
    #pragma unroll
    for (int q = 0; q < 4; q++) {
        unpack2(sacc[2 * q], a0, a1); unpack2(sacc[2 * q + 1], a2, a3);
        asm volatile("red.global.add.v4.f32 [%0], {%1,%2,%3,%4};"
                     :: "l"(sp + 4 * q), "f"(a0), "f"(a1), "f"(a2), "f"(a3) : "memory");
    }
}

// out = squash(s2); re-zero all scratch for graph-replay determinism
__global__ void final_kernel(float* __restrict__ out)
{
    int t = blockIdx.x * blockDim.x + threadIdx.x;
    if (t < BATCH * NUM_CAPS) {
        float4* sp = (float4*)(g_sbuf[2] + t * DIM_VEC);
        float4 s4[4]; float sq = 0.f;
        #pragma unroll
        for (int q = 0; q < 4; q++) {
            s4[q] = sp[q];
            sq = fmaf(s4[q].x, s4[q].x, sq); sq = fmaf(s4[q].y, s4[q].y, sq);
            sq = fmaf(s4[q].z, s4[q].z, sq); sq = fmaf(s4[q].w, s4[q].w, sq);
        }
        float scale = sq / (1.f + sq) * rsqrtf(sq + EPS);
        float4* dst = (float4*)(out + t * DIM_VEC);
        float4 z = make_float4(0.f, 0.f, 0.f, 0.f);
        #pragma unroll
        for (int q = 0; q < 4; q++) {
            float4 o; o.x = scale * s4[q].x; o.y = scale * s4[q].y;
                      o.z = scale * s4[q].z; o.w = scale * s4[q].w;
            dst[q] = o;
            sp[q] = z;
        }
    }
    if (t < BATCH * NUM_CAPS * DIM_VEC) {
        g_sbuf[0][t] = 0.f;
        g_sbuf[1][t] = 0.f;
    }
}

extern "C" void kernel_launch(void* const* d_in, const int* in_sizes, int n_in,
                              void* d_out, int out_size)
{
    const float* x = nullptr; const float* W = nullptr; const float* bias = nullptr;
    for (int k = 0; k < n_in; k++) {
        if (in_sizes[k] == BATCH * IN_CAPS * 8)                    x    = (const float*)d_in[k];
        else if (in_sizes[k] == IN_CAPS * NUM_CAPS * DIM_VEC * 8)  W    = (const float*)d_in[k];
        else if (in_sizes[k] == IN_CAPS * NUM_CAPS)                bias = (const float*)d_in[k];
    }
    float* out = (float*)d_out;

    cudaFuncSetAttribute(pass_kernel<0>, cudaFuncAttributeMaxDynamicSharedMemorySize, SMEM_BYTES);
    cudaFuncSetAttribute(pass_kernel<1>, cudaFuncAttributeMaxDynamicSharedMemorySize, SMEM_BYTES);
    cudaFuncSetAttribute(pass_kernel<2>, cudaFuncAttributeMaxDynamicSharedMemorySize, SMEM_BYTES);

    dim3 grd(NBLK_I, NBLK_B);
    pass_kernel<0><<<grd, NTH, SMEM_BYTES>>>(x, W, bias);
    pass_kernel<1><<<grd, NTH, SMEM_BYTES>>>(x, W, bias);
    pass_kernel<2><<<grd, NTH, SMEM_BYTES>>>(x, W, bias);
    final_kernel<<<(BATCH * NUM_CAPS * DIM_VEC + 255) / 256, 256>>>(out);
}

// round 10
// speedup vs baseline: 1.5028x; 1.0635x over previous
#include <cuda_runtime.h>

#define BATCH    256
#define IN_CAPS  1152
#define NUM_CAPS 10
#define DIM_VEC  16
#define ITILE    16
#define NBLK_I   (IN_CAPS / ITILE)    // 72
#define B_TILE   32
#define NBLK_B   (BATCH / B_TILE)     // 8
#define NTH      (B_TILE * NUM_CAPS)  // 320
#define EPS 1e-7f

// Shared carve-up (floats)
#define WS_F   (ITILE * NUM_CAPS * 8 * DIM_VEC)  // 20480 : [ii][c][e][d16]
#define XS_F   (B_TILE * 132)                    // 4224  : [bb][j] stride 132 (4-wf LDS.128)
#define EX_F   (4 * B_TILE * 11)                 // 1408  : [slot][bb][c] stride 11
#define CF_F   (ITILE * NUM_CAPS)                // 160   : coef0 tile (pass0)
#define SMEM_BYTES ((WS_F + XS_F + EX_F + CF_F) * 4)   // 105088 B

__device__ float g_sbuf[3][BATCH * NUM_CAPS * DIM_VEC];   // zero-init; final re-zeros
__device__ float g_blog[IN_CAPS * NUM_CAPS * BATCH];      // [i][c][b] : stores b1+bias

using ull = unsigned long long;
__device__ __forceinline__ ull pack2(float lo, float hi) {
    ull r; asm("mov.b64 %0,{%1,%2};" : "=l"(r) : "f"(lo), "f"(hi)); return r;
}
__device__ __forceinline__ ull dup2(float v) {
    ull r; asm("mov.b64 %0,{%1,%1};" : "=l"(r) : "f"(v)); return r;
}
__device__ __forceinline__ void unpack2(ull v, float& lo, float& hi) {
    asm("mov.b64 {%0,%1},%2;" : "=f"(lo), "=f"(hi) : "l"(v));
}
__device__ __forceinline__ ull ffma2(ull a, ull b, ull c) {
    ull d; asm("fma.rn.f32x2 %0,%1,%2,%3;" : "=l"(d) : "l"(a), "l"(b), "l"(c)); return d;
}

// PASS 0: s0 += softmax_c(bias) * u_hat            (no in-loop barriers/exchange)
// PASS 1: v1=squash(s0); b1 = uh.v1 + 2*bias; blog=b1+bias; s1 += softmax(b1)*u_hat
// PASS 2: v2=squash(s1); b2 = uh.v2 + blog;                 s2 += softmax(b2)*u_hat
template <int PASS>
__global__ void __launch_bounds__(NTH, 2)
pass_kernel(const float* __restrict__ x,     // [256,1152,8]
            const float* __restrict__ W,     // [1152,10,16,8]
            const float* __restrict__ bias)  // [1152,10]
{
    extern __shared__ __align__(16) float sh[];
    float* ws  = sh;                          // W tile [ii][c][e][d16]
    float* xs  = sh + WS_F;                   // x tile [bb][j] stride 132
    float* exs = sh + WS_F + XS_F;            // exchange [4][bb][c] stride 11
    float* cfs = exs + EX_F;                  // coef0 tile [ii][c] (pass0 only)

    const int tid = threadIdx.x;
    const int bb  = tid & 31;                 // lane = batch in tile
    const int c   = tid >> 5;                 // warp = capsule
    const int i0  = blockIdx.x * ITILE;
    const int b0  = blockIdx.y * B_TILE;
    const int b   = b0 + bb;

    // ---- Stage W tile: global [i][c][d][e] (float4 = d,e0..3) -> ws[ii][c][e][d]
    {
        const float4* Wg = (const float4*)(W + (size_t)i0 * NUM_CAPS * DIM_VEC * 8);
        #pragma unroll 2
        for (int k = tid; k < ITILE * NUM_CAPS * DIM_VEC * 2; k += NTH) {
            float4 w4 = Wg[k];                // coalesced LDG.128
            int ii = k / (NUM_CAPS * DIM_VEC * 2);
            int r  = k - ii * (NUM_CAPS * DIM_VEC * 2);
            int cc = r >> 5;
            int d  = (r >> 1) & 15;
            int e0 = (r & 1) * 4;
            float* dst = ws + (((ii * NUM_CAPS + cc) * 8) + e0) * DIM_VEC + d;
            dst[0 * DIM_VEC] = w4.x;
            dst[1 * DIM_VEC] = w4.y;
            dst[2 * DIM_VEC] = w4.z;
            dst[3 * DIM_VEC] = w4.w;
        }
    }
    // ---- Stage x tile: xs[bb][j] (row stride 132 -> optimal 4-wf LDS.128 reads)
    for (int t = tid; t < B_TILE * ITILE * 8; t += NTH) {
        int lb = t >> 7;
        int j  = t & 127;
        xs[lb * 132 + j] = x[(size_t)(b0 + lb) * (IN_CAPS * 8) + i0 * 8 + j];
    }
    // ---- Pass0: coef0[ii][c] = softmax_c(bias[i0+ii, :]) computed by ITILE threads
    if (PASS == 0 && tid < ITILE) {
        const float* bp = bias + (i0 + tid) * NUM_CAPS;
        float ex[NUM_CAPS]; float den = 0.f;
        #pragma unroll
        for (int k = 0; k < NUM_CAPS; k++) { ex[k] = __expf(bp[k]); den += ex[k]; }
        float inv = __frcp_rn(den);
        #pragma unroll
        for (int k = 0; k < NUM_CAPS; k++) cfs[tid * NUM_CAPS + k] = ex[k] * inv;
    }

    // PDL: our staging is done (only reads x/W/bias) -> let the next kernel launch
    // and do ITS staging while we compute.
    cudaTriggerProgrammaticLaunchCompletion();

    ull vv[8];
    if (PASS > 0) {
        // Wait for predecessor (its red.global.adds to g_sbuf[PASS-1] must be visible)
        cudaGridDependencySynchronize();
        const float4* sp = (const float4*)(g_sbuf[PASS - 1] + (b * NUM_CAPS + c) * DIM_VEC);
        float4 s4[4]; float sq = 0.f;
        #pragma unroll
        for (int q = 0; q < 4; q++) {
            s4[q] = sp[q];
            sq = fmaf(s4[q].x, s4[q].x, sq); sq = fmaf(s4[q].y, s4[q].y, sq);
            sq = fmaf(s4[q].z, s4[q].z, sq); sq = fmaf(s4[q].w, s4[q].w, sq);
        }
        float scale = sq / (1.f + sq) * rsqrtf(sq + EPS);
        #pragma unroll
        for (int q = 0; q < 4; q++) {
            vv[2 * q]     = pack2(scale * s4[q].x, scale * s4[q].y);
            vv[2 * q + 1] = pack2(scale * s4[q].z, scale * s4[q].w);
        }
    }
    __syncthreads();

    ull sacc[8];
    #pragma unroll
    for (int p = 0; p < 8; p++) sacc[p] = 0ull;

    if (PASS == 0) {
        // barrier-free streaming; unroll 2 for cross-ii ILP (no vv -> regs available)
        #pragma unroll 2
        for (int ii = 0; ii < ITILE; ii++) {
            const float4* xr = (const float4*)(xs + bb * 132 + ii * 8);
            float4 xa = xr[0], xb = xr[1];
            ull x2[8];
            x2[0] = dup2(xa.x); x2[1] = dup2(xa.y); x2[2] = dup2(xa.z); x2[3] = dup2(xa.w);
            x2[4] = dup2(xb.x); x2[5] = dup2(xb.y); x2[6] = dup2(xb.z); x2[7] = dup2(xb.w);
            ull uh[8];
            #pragma unroll
            for (int p = 0; p < 8; p++) uh[p] = 0ull;
            const ulonglong2* wp = (const ulonglong2*)(ws + ((ii * NUM_CAPS + c) * 8) * DIM_VEC);
            #pragma unroll
            for (int e = 0; e < 8; e++) {
                #pragma unroll
                for (int q = 0; q < 4; q++) {
                    ulonglong2 wv = wp[e * 4 + q];
                    uh[2 * q]     = ffma2(wv.x, x2[e], uh[2 * q]);
                    uh[2 * q + 1] = ffma2(wv.y, x2[e], uh[2 * q + 1]);
                }
            }
            float coef = cfs[ii * NUM_CAPS + c];              // warp-uniform LDS
            ull cf = dup2(coef);
            #pragma unroll
            for (int p = 0; p < 8; p++) sacc[p] = ffma2(cf, uh[p], sacc[p]);
        }
        cudaGridDependencySynchronize();   // prior replay's final must finish zeroing s0
    } else {
        // 2-ii software pipeline: one barrier per pair, 4-slot WAR-safe exchange
        #pragma unroll 1
        for (int iip = 0; iip < ITILE / 2; iip++) {
            const int slot0 = (iip & 1) * 2;
            ull uhA[8], uhB[8];
            float exA, exB;
            #pragma unroll
            for (int sub = 0; sub < 2; sub++) {
                const int ii = 2 * iip + sub;
                const int i  = i0 + ii;
                ull* uh = sub ? uhB : uhA;
                const float4* xr = (const float4*)(xs + bb * 132 + ii * 8);
                float4 xa = xr[0], xb = xr[1];
                ull x2[8];
                x2[0] = dup2(xa.x); x2[1] = dup2(xa.y); x2[2] = dup2(xa.z); x2[3] = dup2(xa.w);
                x2[4] = dup2(xb.x); x2[5] = dup2(xb.y); x2[6] = dup2(xb.z); x2[7] = dup2(xb.w);
                #pragma unroll
                for (int p = 0; p < 8; p++) uh[p] = 0ull;
                const ulonglong2* wp = (const ulonglong2*)(ws + ((ii * NUM_CAPS + c) * 8) * DIM_VEC);
                #pragma unroll
                for (int e = 0; e < 8; e++) {
                    #pragma unroll
                    for (int q = 0; q < 4; q++) {
                        ulonglong2 wv = wp[e * 4 + q];
                        uh[2 * q]     = ffma2(wv.x, x2[e], uh[2 * q]);
                        uh[2 * q + 1] = ffma2(wv.y, x2[e], uh[2 * q + 1]);
                    }
                }
                // agreement from register-resident v
                ull ag = 0ull;
                #pragma unroll
                for (int p = 0; p < 8; p++) ag = ffma2(uh[p], vv[p], ag);
                float alo, ahi; unpack2(ag, alo, ahi);
                float agr = alo + ahi;

                float bnew;
                if (PASS == 1) {
                    const float bs = __ldg(&bias[i * NUM_CAPS + c]);   // warp-uniform
                    bnew = agr + 2.f * bs;
                    g_blog[(i * NUM_CAPS + c) * BATCH + b] = bnew + bs; // b1+bias for pass2
                } else {
                    bnew = agr + g_blog[(i * NUM_CAPS + c) * BATCH + b];
                }
                float ex = __expf(bnew);                      // no max-subtract: bounded
                exs[((slot0 + sub) * B_TILE + bb) * 11 + c] = ex;
                if (sub == 0) exA = ex; else exB = ex;
            }
            __syncthreads();                                  // ONE barrier per 2 ii
            #pragma unroll
            for (int sub = 0; sub < 2; sub++) {
                const float* exr = exs + ((slot0 + sub) * B_TILE + bb) * 11;
                float t0 = exr[0], t1 = exr[1], t2 = exr[2], t3 = exr[3], t4 = exr[4];
                float t5 = exr[5], t6 = exr[6], t7 = exr[7], t8 = exr[8], t9 = exr[9];
                float den = ((t0 + t1) + (t2 + t3)) + ((t4 + t5) + (t6 + t7)) + (t8 + t9);
                float coef = __fdividef(sub ? exB : exA, den);
                ull cf = dup2(coef);
                const ull* uh = sub ? uhB : uhA;
                #pragma unroll
                for (int p = 0; p < 8; p++) sacc[p] = ffma2(cf, uh[p], sacc[p]);
            }
        }
    }

    // partial s[b,c,:] : 4 vectored global reductions (72 per address total)
    float* sp = g_sbuf[PASS] + (b * NUM_CAPS + c) * DIM_VEC;
    float a0, a1, a2, a3;
    #pragma unroll
    for (int q = 0; q < 4; q++) {
        unpack2(sacc[2 * q], a0, a1); unpack2(sacc[2 * q + 1], a2, a3);
        asm volatile("red.global.add.v4.f32 [%0], {%1,%2,%3,%4};"
                     :: "l"(sp + 4 * q), "f"(a0), "f"(a1), "f"(a2), "f"(a3) : "memory");
    }
}

// out = squash(s2); re-zero all scratch for graph-replay determinism
__global__ void final_kernel(float* __restrict__ out)
{
    cudaTriggerProgrammaticLaunchCompletion();   // let next replay's pass0 stage early
    cudaGridDependencySynchronize();             // pass2 complete before we read/zero
    int t = blockIdx.x * blockDim.x + threadIdx.x;
    if (t < BATCH * NUM_CAPS) {
        float4* sp = (float4*)(g_sbuf[2] + t * DIM_VEC);
        float4 s4[4]; float sq = 0.f;
        #pragma unroll
        for (int q = 0; q < 4; q++) {
            s4[q] = sp[q];
            sq = fmaf(s4[q].x, s4[q].x, sq); sq = fmaf(s4[q].y, s4[q].y, sq);
            sq = fmaf(s4[q].z, s4[q].z, sq); sq = fmaf(s4[q].w, s4[q].w, sq);
        }
        float scale = sq / (1.f + sq) * rsqrtf(sq + EPS);
        float4* dst = (float4*)(out + t * DIM_VEC);
        float4 z = make_float4(0.f, 0.f, 0.f, 0.f);
        #pragma unroll
        for (int q = 0; q < 4; q++) {
            float4 o; o.x = scale * s4[q].x; o.y = scale * s4[q].y;
                      o.z = scale * s4[q].z; o.w = scale * s4[q].w;
            dst[q] = o;
            sp[q] = z;
        }
    }
    if (t < BATCH * NUM_CAPS * DIM_VEC) {
        g_sbuf[0][t] = 0.f;
        g_sbuf[1][t] = 0.f;
    }
}

extern "C" void kernel_launch(void* const* d_in, const int* in_sizes, int n_in,
                              void* d_out, int out_size)
{
    const float* x = nullptr; const float* W = nullptr; const float* bias = nullptr;
    for (int k = 0; k < n_in; k++) {
        if (in_sizes[k] == BATCH * IN_CAPS * 8)                    x    = (const float*)d_in[k];
        else if (in_sizes[k] == IN_CAPS * NUM_CAPS * DIM_VEC * 8)  W    = (const float*)d_in[k];
        else if (in_sizes[k] == IN_CAPS * NUM_CAPS)                bias = (const float*)d_in[k];
    }
    float* out = (float*)d_out;

    cudaFuncSetAttribute(pass_kernel<0>, cudaFuncAttributeMaxDynamicSharedMemorySize, SMEM_BYTES);
    cudaFuncSetAttribute(pass_kernel<1>, cudaFuncAttributeMaxDynamicSharedMemorySize, SMEM_BYTES);
    cudaFuncSetAttribute(pass_kernel<2>, cudaFuncAttributeMaxDynamicSharedMemorySize, SMEM_BYTES);

    dim3 grd(NBLK_I, NBLK_B);

    cudaLaunchAttribute at[1];
    at[0].id = cudaLaunchAttributeProgrammaticStreamSerialization;
    at[0].val.programmaticStreamSerializationAllowed = 1;

    cudaLaunchConfig_t cfg = {};
    cfg.gridDim = grd;
    cfg.blockDim = dim3(NTH, 1, 1);
    cfg.dynamicSmemBytes = SMEM_BYTES;
    cfg.stream = 0;
    cfg.attrs = at;
    cfg.numAttrs = 1;

    cudaLaunchKernelEx(&cfg, pass_kernel<0>, x, W, bias);
    cudaLaunchKernelEx(&cfg, pass_kernel<1>, x, W, bias);
    cudaLaunchKernelEx(&cfg, pass_kernel<2>, x, W, bias);

    cudaLaunchConfig_t fcfg = {};
    fcfg.gridDim = dim3((BATCH * NUM_CAPS * DIM_VEC + 255) / 256, 1, 1);
    fcfg.blockDim = dim3(256, 1, 1);
    fcfg.dynamicSmemBytes = 0;
    fcfg.stream = 0;
    fcfg.attrs = at;
    fcfg.numAttrs = 1;
    cudaLaunchKernelEx(&fcfg, final_kernel, out);
}